// round 1
// baseline (speedup 1.0000x reference)
#include <cuda_runtime.h>

// ============================================================================
// EcgFilter: notch IIR filtfilt (exact, chunked linear recurrence)
//            + FIR bandpass filtfilt collapsed to a single symmetric 301-tap
//              convolution g = autocorr(b_fir) on the odd-extended signal.
//
// Derivation notes:
//  - FIR filtfilt zi corrections land entirely in the trimmed edge region
//    (forward correction on yf[0:150], outputs read yf[453:]; backward
//    correction on yb[0:150] i.e. final positions > T+755, trimmed at 453).
//    So: out[t] = sum_{d=-150}^{150} g[d] * xe[t+d], g[d]=sum_j b[j]b[j+d],
//    xe = odd extension of the IIR output by 150.
//  - IIR filtfilt done exactly (both passes, zi*x0 init, odd-ext 9, trim 9).
// ============================================================================

#define T_LEN   120000
#define N_ROWS  384
#define EDGE    9
#define TEXT    (T_LEN + 2*EDGE)            // 120018
#define P_CH    256                          // chunks (= threads) per row
#define L_CH    ((TEXT + P_CH - 1) / P_CH)   // 469
#define SA_STRIDE 120032

#define FIR_TAPS 151
#define G_TAPS   301
#define HALO     150
#define F_THREADS 256
#define F_RPT     8
#define F_TILE    (F_THREADS * F_RPT)        // 2048 outputs per block
#define F_SM      (F_TILE + 2*HALO + 8)      // 2356 floats

// Scratch (static __device__ arrays: allocation-free rule)
__device__ float g_yf [(size_t)N_ROWS * SA_STRIDE];  // forward IIR result (ext coords)
__device__ float g_mid[(size_t)N_ROWS * T_LEN];      // IIR filtfilt result
__device__ float g_comb[G_TAPS];                     // autocorr of b_fir

// odd (antisymmetric) extension read: u in [-452, T+452]
__device__ __forceinline__ float odd_ext_load(const float* __restrict__ r, int u)
{
    if (u < 0)       return 2.0f * r[0]         - r[-u];
    if (u >= T_LEN)  return 2.0f * r[T_LEN - 1] - r[2 * T_LEN - 2 - u];
    return r[u];
}

// ============================================================================
// IIR notch filtfilt: one block per row.
//  forward:  ext(x) -> yf (stored in ext coordinates)
//  backward: reverse(yf) -> yb, write final trimmed result to g_mid
// Each direction: phase1 (zero-state chunk runs + A^len), serial affine scan
// over 256 chunk maps by thread 0, phase2 (rerun with correct initial state).
// ============================================================================
__global__ __launch_bounds__(P_CH)
void iir_filtfilt_kernel(const float* __restrict__ x,
                         const float* __restrict__ b,
                         const float* __restrict__ a,
                         const float* __restrict__ zi)
{
    __shared__ float sM00[P_CH], sM01[P_CH], sM10[P_CH], sM11[P_CH];
    __shared__ float sV1[P_CH], sV2[P_CH];
    __shared__ float sZ1[P_CH], sZ2[P_CH];

    const int row = blockIdx.x;
    const int p   = threadIdx.x;
    const float* xr   = x     + (size_t)row * T_LEN;
    float*       yfr  = g_yf  + (size_t)row * SA_STRIDE;
    float*       midr = g_mid + (size_t)row * T_LEN;

    const float b0 = b[0], b1 = b[1], b2 = b[2];
    const float a1 = a[1], a2 = a[2];
    const float zi0 = zi[0], zi1 = zi[1];

    const int s = p * L_CH;
    int len = TEXT - s;
    len = len < L_CH ? len : L_CH;
    len = len < 0 ? 0 : len;

    // M = A^len, A = [[-a1, 1], [-a2, 0]]  (binary exponentiation; powers commute)
    {
        float c00 = -a1, c01 = 1.f, c10 = -a2, c11 = 0.f;
        float r00 = 1.f, r01 = 0.f, r10 = 0.f, r11 = 1.f;
        int e = len;
        while (e) {
            if (e & 1) {
                float t00 = r00*c00 + r01*c10;
                float t01 = r00*c01 + r01*c11;
                float t10 = r10*c00 + r11*c10;
                float t11 = r10*c01 + r11*c11;
                r00 = t00; r01 = t01; r10 = t10; r11 = t11;
            }
            e >>= 1;
            if (e) {
                float t00 = c00*c00 + c01*c10;
                float t01 = c00*c01 + c01*c11;
                float t10 = c10*c00 + c11*c10;
                float t11 = c10*c01 + c11*c11;
                c00 = t00; c01 = t01; c10 = t10; c11 = t11;
            }
        }
        sM00[p] = r00; sM01[p] = r01; sM10[p] = r10; sM11[p] = r11;
    }

    // ---------------- FORWARD ----------------
    {   // phase 1: zero-state chunk run -> v_p
        float z1 = 0.f, z2 = 0.f;
        for (int i = s; i < s + len; ++i) {
            float xn = odd_ext_load(xr, i - EDGE);
            float y  = fmaf(b0, xn, z1);
            float n1 = fmaf(b1, xn, z2) - a1 * y;
            float n2 = b2 * xn - a2 * y;
            z1 = n1; z2 = n2;
        }
        sV1[p] = z1; sV2[p] = z2;
    }
    __syncthreads();
    if (p == 0) {   // serial scan of 256 affine chunk maps
        float e0 = odd_ext_load(xr, -EDGE);
        float z1 = zi0 * e0, z2 = zi1 * e0;
        for (int q = 0; q < P_CH; ++q) {
            sZ1[q] = z1; sZ2[q] = z2;
            float n1 = sM00[q]*z1 + sM01[q]*z2 + sV1[q];
            float n2 = sM10[q]*z1 + sM11[q]*z2 + sV2[q];
            z1 = n1; z2 = n2;
        }
    }
    __syncthreads();
    {   // phase 2: rerun with correct incoming state, emit yf
        float z1 = sZ1[p], z2 = sZ2[p];
        for (int i = s; i < s + len; ++i) {
            float xn = odd_ext_load(xr, i - EDGE);
            float y  = fmaf(b0, xn, z1);
            yfr[i] = y;
            float n1 = fmaf(b1, xn, z2) - a1 * y;
            float n2 = b2 * xn - a2 * y;
            z1 = n1; z2 = n2;
        }
    }
    __syncthreads();   // yf visible block-wide

    // ---------------- BACKWARD (stream = reversed yf) ----------------
    {   // phase 1
        float z1 = 0.f, z2 = 0.f;
        for (int i = s; i < s + len; ++i) {
            float xn = yfr[TEXT - 1 - i];
            float y  = fmaf(b0, xn, z1);
            float n1 = fmaf(b1, xn, z2) - a1 * y;
            float n2 = b2 * xn - a2 * y;
            z1 = n1; z2 = n2;
        }
        sV1[p] = z1; sV2[p] = z2;
    }
    __syncthreads();
    if (p == 0) {
        float e0 = yfr[TEXT - 1];
        float z1 = zi0 * e0, z2 = zi1 * e0;
        for (int q = 0; q < P_CH; ++q) {
            sZ1[q] = z1; sZ2[q] = z2;
            float n1 = sM00[q]*z1 + sM01[q]*z2 + sV1[q];
            float n2 = sM10[q]*z1 + sM11[q]*z2 + sV2[q];
            z1 = n1; z2 = n2;
        }
    }
    __syncthreads();
    {   // phase 2: emit final trimmed result (yb reversed, trim 9 each side)
        float z1 = sZ1[p], z2 = sZ2[p];
        for (int i = s; i < s + len; ++i) {
            float xn = yfr[TEXT - 1 - i];
            float y  = fmaf(b0, xn, z1);
            int t = TEXT - 10 - i;          // final output index
            if (t >= 0 && t < T_LEN) midr[t] = y;
            float n1 = fmaf(b1, xn, z2) - a1 * y;
            float n2 = b2 * xn - a2 * y;
            z1 = n1; z2 = n2;
        }
    }
}

// ============================================================================
// g[d] = autocorrelation of b_fir, d = k-150 in [-150, 150]
// ============================================================================
__global__ void comb_kernel(const float* __restrict__ bf)
{
    int k = threadIdx.x;
    if (k >= G_TAPS) return;
    int d  = k - HALO;
    int j0 = d < 0 ? -d : 0;
    int j1 = d < 0 ? (FIR_TAPS - 1) : (FIR_TAPS - 1 - d);
    float acc = 0.f;
    for (int j = j0; j <= j1; ++j)
        acc = fmaf(bf[j], bf[j + d], acc);
    g_comb[k] = acc;
}

// ============================================================================
// Symmetric 301-tap convolution on odd-extended g_mid -> d_out.
// Block = 2048 outputs (256 thr x 8/thread), smem tile + rotating register
// window (1 LDS per 8 FFMA). fma-pipe bound by design.
// ============================================================================
__global__ __launch_bounds__(F_THREADS)
void fir_kernel(float* __restrict__ out)
{
    __shared__ float sT[F_SM];
    __shared__ float sG[G_TAPS];

    const int row = blockIdx.y;
    const int t0  = blockIdx.x * F_TILE;
    const float* xr   = g_mid + (size_t)row * T_LEN;
    float*       outr = out   + (size_t)row * T_LEN;

    for (int j = threadIdx.x; j < F_TILE + 2 * HALO; j += F_THREADS)
        sT[j] = odd_ext_load(xr, t0 - HALO + j);
    for (int j = threadIdx.x; j < G_TAPS; j += F_THREADS)
        sG[j] = g_comb[j];
    __syncthreads();

    const int base = threadIdx.x * F_RPT;
    float acc[F_RPT];
    float w[F_RPT];
    #pragma unroll
    for (int r = 0; r < F_RPT; ++r) { acc[r] = 0.f; w[r] = sT[base + r]; }

    // rotating window: at tap k, w[(k+r)&7] == sT[base+k+r]
    #pragma unroll 1
    for (int kb = 0; kb < 296; kb += 8) {
        #pragma unroll
        for (int kk = 0; kk < 8; ++kk) {
            float gk = sG[kb + kk];
            #pragma unroll
            for (int r = 0; r < F_RPT; ++r)
                acc[r] = fmaf(gk, w[(r + kk) & 7], acc[r]);
            w[kk] = sT[base + kb + kk + 8];
        }
    }
    // tail taps 296..300
    #pragma unroll
    for (int k = 296; k < G_TAPS; ++k) {
        float gk = sG[k];
        #pragma unroll
        for (int r = 0; r < F_RPT; ++r)
            acc[r] = fmaf(gk, sT[base + k + r], acc[r]);
    }

    const int tg = t0 + base;
    #pragma unroll
    for (int r = 0; r < F_RPT; ++r) {
        int t = tg + r;
        if (t < T_LEN) outr[t] = acc[r];
    }
}

// ============================================================================
// Inputs (metadata order): x, b_notch(3), a_notch(3), zi_notch(2),
//                          b_fir(151), zi_fir(150, provably unused)
// ============================================================================
extern "C" void kernel_launch(void* const* d_in, const int* in_sizes, int n_in,
                              void* d_out, int out_size)
{
    const float* x  = (const float*)d_in[0];
    const float* bn = (const float*)d_in[1];
    const float* an = (const float*)d_in[2];
    const float* zn = (const float*)d_in[3];
    const float* bf = (const float*)d_in[4];
    float* out = (float*)d_out;

    iir_filtfilt_kernel<<<N_ROWS, P_CH>>>(x, bn, an, zn);
    comb_kernel<<<1, 320>>>(bf);
    dim3 fgrid((T_LEN + F_TILE - 1) / F_TILE, N_ROWS);
    fir_kernel<<<fgrid, F_THREADS>>>(out);
}